// round 1
// baseline (speedup 1.0000x reference)
#include <cuda_runtime.h>
#include <cuda_bf16.h>
#include <math.h>

// Problem constants
#define BZ 32
#define TT 256
#define EE 1024
#define HH 1024
#define KK 2048   // per-layer K: [h0 ; x_t] for layer0, [h0 ; h1] for layer1
#define C4 4096   // 4*H gate columns per layer

// ---------------------------------------------------------------------------
// Scratch (device globals; no allocations allowed)
// ---------------------------------------------------------------------------
// Weights pre-transposed to [layer][col][k], split into bf16 hi/lo.
//   layer0: k<1024 -> W_hh0[k][col],  k>=1024 -> W_ih0[k-1024][col]
//   layer1: k<1024 -> W_ih1[k][col],  k>=1024 -> W_hh1[k-1024][col]
__device__ __nv_bfloat16 g_Wt_hi[2][C4][KK];
__device__ __nv_bfloat16 g_Wt_lo[2][C4][KK];
// x re-laid-out as [t*32 + b][e], split hi/lo
__device__ __nv_bfloat16 g_x_hi[TT * BZ][EE];
__device__ __nv_bfloat16 g_x_lo[TT * BZ][EE];
// hidden states as bf16 hi/lo, ping-pong on parity to avoid intra-step races
__device__ __nv_bfloat16 g_hbf_hi[2][2][BZ][HH];   // [parity][layer][b][j]
__device__ __nv_bfloat16 g_hbf_lo[2][2][BZ][HH];
// fp32 master states
__device__ float g_h[2][BZ][HH];
__device__ float g_c[2][BZ][HH];

// ---------------------------------------------------------------------------
// Helpers
// ---------------------------------------------------------------------------
__device__ __forceinline__ unsigned ldu(const __nv_bfloat16* p) {
    return *reinterpret_cast<const unsigned*>(p);
}

__device__ __forceinline__ void mma16816(float d[4], const unsigned a[4],
                                         unsigned b0, unsigned b1) {
    asm volatile(
        "mma.sync.aligned.m16n8k16.row.col.f32.bf16.bf16.f32 "
        "{%0,%1,%2,%3}, {%4,%5,%6,%7}, {%8,%9}, {%0,%1,%2,%3};\n"
        : "+f"(d[0]), "+f"(d[1]), "+f"(d[2]), "+f"(d[3])
        : "r"(a[0]), "r"(a[1]), "r"(a[2]), "r"(a[3]), "r"(b0), "r"(b1));
}

// One K=1024 segment: 3-term split accumulation (hi*hi + hi*lo + lo*hi).
// A pointers already include the per-thread k offset (ka).
__device__ __forceinline__ void gemm_k1024(
    float acc0[4], float acc1[4],
    const __nv_bfloat16* __restrict__ A0hi, const __nv_bfloat16* __restrict__ A1hi,
    const __nv_bfloat16* __restrict__ A0lo, const __nv_bfloat16* __restrict__ A1lo,
    const __nv_bfloat16* __restrict__ Bhi,  const __nv_bfloat16* __restrict__ Blo,
    int n0, int n1, int ka)
{
    const __nv_bfloat16* B0h = Bhi + (size_t)n0 * HH + ka;
    const __nv_bfloat16* B1h = Bhi + (size_t)n1 * HH + ka;
    const __nv_bfloat16* B0l = Blo + (size_t)n0 * HH + ka;
    const __nv_bfloat16* B1l = Blo + (size_t)n1 * HH + ka;
#pragma unroll 4
    for (int kc = 0; kc < HH; kc += 16) {
        unsigned ahi[4], alo[4];
        ahi[0] = ldu(A0hi + kc);     ahi[1] = ldu(A1hi + kc);
        ahi[2] = ldu(A0hi + kc + 8); ahi[3] = ldu(A1hi + kc + 8);
        alo[0] = ldu(A0lo + kc);     alo[1] = ldu(A1lo + kc);
        alo[2] = ldu(A0lo + kc + 8); alo[3] = ldu(A1lo + kc + 8);

        unsigned bh0a = ldu(B0h + kc), bh0b = ldu(B0h + kc + 8);
        unsigned bh1a = ldu(B1h + kc), bh1b = ldu(B1h + kc + 8);
        unsigned bl0a = ldu(B0l + kc), bl0b = ldu(B0l + kc + 8);
        unsigned bl1a = ldu(B1l + kc), bl1b = ldu(B1l + kc + 8);

        mma16816(acc0, ahi, bh0a, bh0b);
        mma16816(acc0, ahi, bl0a, bl0b);
        mma16816(acc0, alo, bh0a, bh0b);
        mma16816(acc1, ahi, bh1a, bh1b);
        mma16816(acc1, ahi, bl1a, bl1b);
        mma16816(acc1, alo, bh1a, bh1b);
    }
}

// ---------------------------------------------------------------------------
// Prep kernels (run every launch; deterministic)
// ---------------------------------------------------------------------------
__global__ void prep_weights(const float* __restrict__ W_ih0,
                             const float* __restrict__ W_hh0,
                             const float* __restrict__ W_ih1,
                             const float* __restrict__ W_hh1)
{
    // block (32,8): 32x32 tile transpose with split
    __shared__ float tile[32][33];
    int k0 = blockIdx.x * 32;
    int c0 = blockIdx.y * 32;
    int L  = blockIdx.z;
    int tx = threadIdx.x, ty = threadIdx.y;
#pragma unroll
    for (int i = 0; i < 4; i++) {
        int k = k0 + ty + i * 8;
        const float* S; int kr;
        if (L == 0) { if (k < HH) { S = W_hh0; kr = k; } else { S = W_ih0; kr = k - HH; } }
        else        { if (k < HH) { S = W_ih1; kr = k; } else { S = W_hh1; kr = k - HH; } }
        tile[ty + i * 8][tx] = S[(size_t)kr * C4 + c0 + tx];
    }
    __syncthreads();
#pragma unroll
    for (int i = 0; i < 4; i++) {
        int c = c0 + ty + i * 8;
        float v = tile[tx][ty + i * 8];
        __nv_bfloat16 hi = __float2bfloat16(v);
        g_Wt_hi[L][c][k0 + tx] = hi;
        g_Wt_lo[L][c][k0 + tx] = __float2bfloat16(v - __bfloat162float(hi));
    }
}

__global__ void prep_x(const float* __restrict__ x)
{
    const int N = BZ * TT * EE;
    for (int idx = blockIdx.x * blockDim.x + threadIdx.x; idx < N;
         idx += gridDim.x * blockDim.x) {
        int e  = idx & (EE - 1);
        int bt = idx >> 10;          // b*TT + t
        int t  = bt & (TT - 1);
        int b  = bt >> 8;
        float v = x[idx];
        __nv_bfloat16 hi = __float2bfloat16(v);
        size_t d = ((size_t)t * BZ + b) * EE + e;
        (&g_x_hi[0][0])[d] = hi;
        (&g_x_lo[0][0])[d] = __float2bfloat16(v - __bfloat162float(hi));
    }
}

__global__ void zero_states()
{
    int idx = blockIdx.x * blockDim.x + threadIdx.x;
    const int nbf = 2 * 2 * BZ * HH;     // 131072
    if (idx < nbf) {
        (&g_hbf_hi[0][0][0][0])[idx] = __float2bfloat16(0.f);
        (&g_hbf_lo[0][0][0][0])[idx] = __float2bfloat16(0.f);
    }
    const int nf = 2 * BZ * HH;          // 65536
    if (idx < nf) {
        (&g_h[0][0][0])[idx] = 0.f;
        (&g_c[0][0][0])[idx] = 0.f;
    }
}

__global__ void copy_mask(const float* __restrict__ m, float* __restrict__ dst)
{
    int i = blockIdx.x * blockDim.x + threadIdx.x;
    if (i < BZ * TT) dst[i] = m[i];
}

// ---------------------------------------------------------------------------
// One timestep: both cells (they only read t-1 state). 256 blocks x 128 thr.
// Block bx: layer = bx>>7, units [u0, u0+8); computes the 32 gate columns
// (f,i,o,g for 8 units) x 32 batch via split-bf16 mma, then fused pointwise.
// ---------------------------------------------------------------------------
__global__ void __launch_bounds__(128) lstm_step(
    int t,
    const float* __restrict__ mask,
    const float* __restrict__ bias0,
    const float* __restrict__ bias1,
    float* __restrict__ out)
{
    __shared__ float preS[32][33];

    const int bx    = blockIdx.x;
    const int layer = bx >> 7;
    const int u0    = (bx & 127) * 8;
    const int tid   = threadIdx.x;
    const int lane  = tid & 31;
    const int warp  = tid >> 5;
    const int wm    = warp >> 1;   // m-half (0: f,i rows ; 1: o,g rows)
    const int wn    = warp & 1;    // n-half (batch 0-15 / 16-31)
    const int p     = t & 1;

    // A row -> weight column mapping: row r in [0,32): col = (r>>3)*H + u0 + (r&7)
    const int r0   = wm * 16 + (lane >> 2);
    const int r1   = r0 + 8;
    const int col0 = (r0 >> 3) * HH + u0 + (r0 & 7);
    const int col1 = (r1 >> 3) * HH + u0 + (r1 & 7);
    const int ka   = (lane & 3) * 2;

    const __nv_bfloat16* Whi = &g_Wt_hi[layer][0][0];
    const __nv_bfloat16* Wlo = &g_Wt_lo[layer][0][0];
    const __nv_bfloat16* A0hi = Whi + (size_t)col0 * KK + ka;
    const __nv_bfloat16* A1hi = Whi + (size_t)col1 * KK + ka;
    const __nv_bfloat16* A0lo = Wlo + (size_t)col0 * KK + ka;
    const __nv_bfloat16* A1lo = Wlo + (size_t)col1 * KK + ka;

    // B sources: k<1024 -> h0(prev) for BOTH layers; k>=1024 -> x_t (L0) / h1(prev) (L1)
    const __nv_bfloat16* Bh0_hi = &g_hbf_hi[p][0][0][0];
    const __nv_bfloat16* Bh0_lo = &g_hbf_lo[p][0][0][0];
    const __nv_bfloat16* Bhk_hi = layer ? &g_hbf_hi[p][1][0][0] : &g_x_hi[(size_t)t * BZ][0];
    const __nv_bfloat16* Bhk_lo = layer ? &g_hbf_lo[p][1][0][0] : &g_x_lo[(size_t)t * BZ][0];

    const int n0 = wn * 16 + (lane >> 2);
    const int n1 = n0 + 8;

    float acc0[4] = {0.f, 0.f, 0.f, 0.f};
    float acc1[4] = {0.f, 0.f, 0.f, 0.f};

    // K segment 0: recurrent h0
    gemm_k1024(acc0, acc1, A0hi, A1hi, A0lo, A1lo, Bh0_hi, Bh0_lo, n0, n1, ka);
    // K segment 1: x_t (layer0) or h1 (layer1)
    gemm_k1024(acc0, acc1, A0hi + HH, A1hi + HH, A0lo + HH, A1lo + HH,
               Bhk_hi, Bhk_lo, n0, n1, ka);

    // Scatter accumulators: preS[gate-row][batch]
    {
        const int drow = wm * 16 + (lane >> 2);
        const int dcol = wn * 16 + (lane & 3) * 2;
        preS[drow][dcol]         = acc0[0];
        preS[drow][dcol + 1]     = acc0[1];
        preS[drow + 8][dcol]     = acc0[2];
        preS[drow + 8][dcol + 1] = acc0[3];
        preS[drow][dcol + 8]         = acc1[0];
        preS[drow][dcol + 9]         = acc1[1];
        preS[drow + 8][dcol + 8]     = acc1[2];
        preS[drow + 8][dcol + 9]     = acc1[3];
    }
    __syncthreads();

    // Fused pointwise LSTM cell update (8 units x 32 batch = 256 elems)
    const float* bias = layer ? bias1 : bias0;
#pragma unroll
    for (int e = tid; e < 256; e += 128) {
        const int du = e >> 5;
        const int b  = e & 31;
        const int j  = u0 + du;
        float f = preS[du][b]          + bias[j];
        float i = preS[8 + du][b]      + bias[HH + j];
        float o = preS[16 + du][b]     + bias[2 * HH + j];
        float g = preS[24 + du][b]     + bias[3 * HH + j];
        const float m  = mask[b * TT + t];
        const float cp = g_c[layer][b][j];
        const float hp = g_h[layer][b][j];

        const float sf = 1.f / (1.f + expf(-f));
        const float si = 1.f / (1.f + expf(-i));
        const float so = 1.f / (1.f + expf(-o));

        float cn = sf * cp + si * tanhf(g);
        cn = cn * m + cp * (1.f - m);
        float hn = so * tanhf(cn);
        hn = hn * m + hp * (1.f - m);

        g_c[layer][b][j] = cn;
        g_h[layer][b][j] = hn;
        const __nv_bfloat16 hh = __float2bfloat16(hn);
        g_hbf_hi[p ^ 1][layer][b][j] = hh;
        g_hbf_lo[p ^ 1][layer][b][j] = __float2bfloat16(hn - __bfloat162float(hh));
        if (layer) out[((size_t)b * TT + t) * HH + j] = hn;
    }
}

// ---------------------------------------------------------------------------
extern "C" void kernel_launch(void* const* d_in, const int* in_sizes, int n_in,
                              void* d_out, int out_size)
{
    const float* x     = (const float*)d_in[0];
    const float* mask  = (const float*)d_in[1];
    const float* W_ih0 = (const float*)d_in[2];
    const float* W_hh0 = (const float*)d_in[3];
    const float* bs0   = (const float*)d_in[4];
    const float* W_ih1 = (const float*)d_in[5];
    const float* W_hh1 = (const float*)d_in[6];
    const float* bs1   = (const float*)d_in[7];
    float* out = (float*)d_out;

    prep_weights<<<dim3(KK / 32, C4 / 32, 2), dim3(32, 8)>>>(W_ih0, W_hh0, W_ih1, W_hh1);
    prep_x<<<1024, 256>>>(x);
    zero_states<<<512, 256>>>();

    for (int t = 0; t < TT; t++) {
        lstm_step<<<256, 128>>>(t, mask, bs0, bs1, out);
    }

    // Reference returns (states, mask); append mask if the output buffer has room.
    if (out_size >= BZ * TT * HH + BZ * TT) {
        copy_mask<<<(BZ * TT + 255) / 256, 256>>>(mask, out + (size_t)BZ * TT * HH);
    }
}

// round 2
// speedup vs baseline: 1.1189x; 1.1189x over previous
#include <cuda_runtime.h>
#include <cuda_bf16.h>
#include <math.h>

// Problem constants
#define BZ 32
#define TT 256
#define EE 1024
#define HH 1024
#define KK 2048   // per-layer K: [h_prev ; other] (other = x_t for L0, h1_prev for L1)
#define C4 4096   // 4*H gate columns per layer

// Tiling: 128 blocks, each = 1 layer-slice of 64 gate-cols (16 units x 4 gates)
// x 32 batch. 4 warps/block; warp w owns gate w for the block's 16 units.
#define NGRP 64           // m-groups per layer (4096 / 64)
#define NCHUNK (KK / 16)  // 128 k-chunks of 16

// ---------------------------------------------------------------------------
// Scratch (device globals; no allocations allowed)
// ---------------------------------------------------------------------------
// Stage-1 transposed weights [layer][col][k], bf16 hi/lo.
//   layer0: k<1024 -> W_hh0[k][col],  k>=1024 -> W_ih0[k-1024][col]
//   layer1: k<1024 -> W_ih1[k][col],  k>=1024 -> W_hh1[k-1024][col]
__device__ __nv_bfloat16 g_Wt_hi[2][C4][KK];
__device__ __nv_bfloat16 g_Wt_lo[2][C4][KK];
// Stage-2 fragment-swizzled weights: index ((((L*64+g)*4+w)*128+c)*32+lane),
// each uint4 = the 4 .b32 words of one lane's m16n8k16 A fragment.
__device__ uint4 g_Wsw_hi[2 * NGRP * 4 * NCHUNK * 32];
__device__ uint4 g_Wsw_lo[2 * NGRP * 4 * NCHUNK * 32];
// x re-laid-out as [t*32 + b][e], split hi/lo
__device__ __nv_bfloat16 g_x_hi[TT * BZ][EE];
__device__ __nv_bfloat16 g_x_lo[TT * BZ][EE];
// hidden states as bf16 hi/lo, ping-pong on parity to avoid intra-step races
__device__ __nv_bfloat16 g_hbf_hi[2][2][BZ][HH];   // [parity][layer][b][j]
__device__ __nv_bfloat16 g_hbf_lo[2][2][BZ][HH];
// fp32 master states
__device__ float g_h[2][BZ][HH];
__device__ float g_c[2][BZ][HH];

// ---------------------------------------------------------------------------
// Helpers
// ---------------------------------------------------------------------------
__device__ __forceinline__ unsigned ldu(const __nv_bfloat16* p) {
    return *reinterpret_cast<const unsigned*>(p);
}

__device__ __forceinline__ void mma16816(float d[4], const unsigned* a,
                                         unsigned b0, unsigned b1) {
    asm volatile(
        "mma.sync.aligned.m16n8k16.row.col.f32.bf16.bf16.f32 "
        "{%0,%1,%2,%3}, {%4,%5,%6,%7}, {%8,%9}, {%0,%1,%2,%3};\n"
        : "+f"(d[0]), "+f"(d[1]), "+f"(d[2]), "+f"(d[3])
        : "r"(a[0]), "r"(a[1]), "r"(a[2]), "r"(a[3]), "r"(b0), "r"(b1));
}

// ---------------------------------------------------------------------------
// Prep kernels (run every launch; deterministic)
// ---------------------------------------------------------------------------
__global__ void prep_weights(const float* __restrict__ W_ih0,
                             const float* __restrict__ W_hh0,
                             const float* __restrict__ W_ih1,
                             const float* __restrict__ W_hh1)
{
    __shared__ float tile[32][33];
    int k0 = blockIdx.x * 32;
    int c0 = blockIdx.y * 32;
    int L  = blockIdx.z;
    int tx = threadIdx.x, ty = threadIdx.y;
#pragma unroll
    for (int i = 0; i < 4; i++) {
        int k = k0 + ty + i * 8;
        const float* S; int kr;
        if (L == 0) { if (k < HH) { S = W_hh0; kr = k; } else { S = W_ih0; kr = k - HH; } }
        else        { if (k < HH) { S = W_ih1; kr = k; } else { S = W_hh1; kr = k - HH; } }
        tile[ty + i * 8][tx] = S[(size_t)kr * C4 + c0 + tx];
    }
    __syncthreads();
#pragma unroll
    for (int i = 0; i < 4; i++) {
        int c = c0 + ty + i * 8;
        float v = tile[tx][ty + i * 8];
        __nv_bfloat16 hi = __float2bfloat16(v);
        g_Wt_hi[L][c][k0 + tx] = hi;
        g_Wt_lo[L][c][k0 + tx] = __float2bfloat16(v - __bfloat162float(hi));
    }
}

// Stage 2: pack weights into per-lane mma A fragments (one uint4 per lane/chunk).
__global__ void swizzle_weights()
{
    const int idx = blockIdx.x * blockDim.x + threadIdx.x;  // [0, 2*64*4*128*32)
    const int lane = idx & 31;
    const int c    = (idx >> 5)  & (NCHUNK - 1);
    const int w    = (idx >> 12) & 3;
    const int g    = (idx >> 14) & (NGRP - 1);
    const int L    = (idx >> 20) & 1;

    const int r  = lane >> 2;          // 0..7
    const int ka = (lane & 3) * 2;
    const int col0 = w * HH + g * 16 + r;        // rows m0 = w*16+r
    const int col1 = col0 + 8;                   // rows m1 = m0+8
    const int k0 = c * 16 + ka;

    uint4 hi, lo;
    hi.x = ldu(&g_Wt_hi[L][col0][k0]);
    hi.y = ldu(&g_Wt_hi[L][col1][k0]);
    hi.z = ldu(&g_Wt_hi[L][col0][k0 + 8]);
    hi.w = ldu(&g_Wt_hi[L][col1][k0 + 8]);
    lo.x = ldu(&g_Wt_lo[L][col0][k0]);
    lo.y = ldu(&g_Wt_lo[L][col1][k0]);
    lo.z = ldu(&g_Wt_lo[L][col0][k0 + 8]);
    lo.w = ldu(&g_Wt_lo[L][col1][k0 + 8]);
    g_Wsw_hi[idx] = hi;
    g_Wsw_lo[idx] = lo;
}

__global__ void prep_x(const float* __restrict__ x)
{
    const int N = BZ * TT * EE;
    for (int idx = blockIdx.x * blockDim.x + threadIdx.x; idx < N;
         idx += gridDim.x * blockDim.x) {
        int e  = idx & (EE - 1);
        int bt = idx >> 10;          // b*TT + t
        int t  = bt & (TT - 1);
        int b  = bt >> 8;
        float v = x[idx];
        __nv_bfloat16 hi = __float2bfloat16(v);
        size_t d = ((size_t)t * BZ + b) * EE + e;
        (&g_x_hi[0][0])[d] = hi;
        (&g_x_lo[0][0])[d] = __float2bfloat16(v - __bfloat162float(hi));
    }
}

__global__ void zero_states()
{
    int idx = blockIdx.x * blockDim.x + threadIdx.x;
    const int nbf = 2 * 2 * BZ * HH;
    if (idx < nbf) {
        (&g_hbf_hi[0][0][0][0])[idx] = __float2bfloat16(0.f);
        (&g_hbf_lo[0][0][0][0])[idx] = __float2bfloat16(0.f);
    }
    const int nf = 2 * BZ * HH;
    if (idx < nf) {
        (&g_h[0][0][0])[idx] = 0.f;
        (&g_c[0][0][0])[idx] = 0.f;
    }
}

__global__ void copy_mask(const float* __restrict__ m, float* __restrict__ dst)
{
    int i = blockIdx.x * blockDim.x + threadIdx.x;
    if (i < BZ * TT) dst[i] = m[i];
}

// ---------------------------------------------------------------------------
// One timestep. 128 blocks x 128 threads, one wave.
// Block bx: L = bx>>6, unit group g = bx&63 (units [g*16, g*16+16)).
// Warp w computes gate w's 16 rows x 32 batch with split-bf16 mma, then the
// block fuses the pointwise LSTM update via SMEM.
// ---------------------------------------------------------------------------
__global__ void __launch_bounds__(128) lstm_step(
    int t,
    const float* __restrict__ mask,
    const float* __restrict__ bias0,
    const float* __restrict__ bias1,
    float* __restrict__ out)
{
    __shared__ float preS[64][33];

    const int bx   = blockIdx.x;
    const int L    = bx >> 6;
    const int g    = bx & (NGRP - 1);
    const int tid  = threadIdx.x;
    const int lane = tid & 31;
    const int w    = tid >> 5;
    const int p    = t & 1;

    // A fragments: fully swizzled, one LDG.128 per chunk per lane.
    const uint4* __restrict__ Ahi =
        g_Wsw_hi + ((size_t)((L * NGRP + g) * 4 + w) * NCHUNK) * 32 + lane;
    const uint4* __restrict__ Alo =
        g_Wsw_lo + ((size_t)((L * NGRP + g) * 4 + w) * NCHUNK) * 32 + lane;

    // B sources: k<1024 -> h0(prev) for BOTH layers; k>=1024 -> x_t (L0) / h1(prev) (L1)
    const __nv_bfloat16* __restrict__ B0h = &g_hbf_hi[p][0][0][0];
    const __nv_bfloat16* __restrict__ B0l = &g_hbf_lo[p][0][0][0];
    const __nv_bfloat16* __restrict__ Bkh = L ? &g_hbf_hi[p][1][0][0]
                                             : &g_x_hi[(size_t)t * BZ][0];
    const __nv_bfloat16* __restrict__ Bkl = L ? &g_hbf_lo[p][1][0][0]
                                             : &g_x_lo[(size_t)t * BZ][0];

    const int brow = lane >> 2;          // batch sub-row 0..7
    const int bk   = (lane & 3) * 2;     // k offset within chunk
    int boff[4];
#pragma unroll
    for (int j = 0; j < 4; j++) boff[j] = (j * 8 + brow) * HH + bk;

    float acc[4][4];
#pragma unroll
    for (int j = 0; j < 4; j++)
#pragma unroll
        for (int q = 0; q < 4; q++) acc[j][q] = 0.f;

    // Half 0: k in [0,1024) — B = h0(prev)
#pragma unroll 4
    for (int c = 0; c < 64; c++) {
        uint4 ah = Ahi[c * 32];
        uint4 al = Alo[c * 32];
        const unsigned* ap = reinterpret_cast<const unsigned*>(&ah);
        const unsigned* lp = reinterpret_cast<const unsigned*>(&al);
        const int kk = c * 16;
#pragma unroll
        for (int j = 0; j < 4; j++) {
            const int off = boff[j] + kk;
            unsigned bh0 = ldu(B0h + off), bh1 = ldu(B0h + off + 8);
            unsigned bl0 = ldu(B0l + off), bl1 = ldu(B0l + off + 8);
            mma16816(acc[j], ap, bh0, bh1);
            mma16816(acc[j], ap, bl0, bl1);
            mma16816(acc[j], lp, bh0, bh1);
        }
    }
    // Half 1: k in [1024,2048) — B = x_t (L0) or h1(prev) (L1)
#pragma unroll 4
    for (int c = 64; c < 128; c++) {
        uint4 ah = Ahi[c * 32];
        uint4 al = Alo[c * 32];
        const unsigned* ap = reinterpret_cast<const unsigned*>(&ah);
        const unsigned* lp = reinterpret_cast<const unsigned*>(&al);
        const int kk = (c - 64) * 16;
#pragma unroll
        for (int j = 0; j < 4; j++) {
            const int off = boff[j] + kk;
            unsigned bh0 = ldu(Bkh + off), bh1 = ldu(Bkh + off + 8);
            unsigned bl0 = ldu(Bkl + off), bl1 = ldu(Bkl + off + 8);
            mma16816(acc[j], ap, bh0, bh1);
            mma16816(acc[j], ap, bl0, bl1);
            mma16816(acc[j], lp, bh0, bh1);
        }
    }

    // Scatter accumulators to SMEM: preS[gate*16 + unit_local][batch]
    {
        const int r = lane >> 2;
        const int q = (lane & 3) * 2;
#pragma unroll
        for (int j = 0; j < 4; j++) {
            const int n = j * 8 + q;
            preS[w * 16 + r][n]         = acc[j][0];
            preS[w * 16 + r][n + 1]     = acc[j][1];
            preS[w * 16 + r + 8][n]     = acc[j][2];
            preS[w * 16 + r + 8][n + 1] = acc[j][3];
        }
    }
    __syncthreads();

    // Fused pointwise LSTM cell update: 16 units x 32 batch = 512 elems
    const float* __restrict__ bias = L ? bias1 : bias0;
#pragma unroll
    for (int e = tid; e < 512; e += 128) {
        const int ul = e >> 5;
        const int b  = e & 31;
        const int j  = g * 16 + ul;
        float f  = preS[ul][b]      + bias[j];
        float i  = preS[16 + ul][b] + bias[HH + j];
        float o  = preS[32 + ul][b] + bias[2 * HH + j];
        float gg = preS[48 + ul][b] + bias[3 * HH + j];
        const float m  = mask[b * TT + t];
        const float cp = g_c[L][b][j];
        const float hp = g_h[L][b][j];

        const float sf = 1.f / (1.f + expf(-f));
        const float si = 1.f / (1.f + expf(-i));
        const float so = 1.f / (1.f + expf(-o));

        float cn = sf * cp + si * tanhf(gg);
        cn = cn * m + cp * (1.f - m);
        float hn = so * tanhf(cn);
        hn = hn * m + hp * (1.f - m);

        g_c[L][b][j] = cn;
        g_h[L][b][j] = hn;
        const __nv_bfloat16 hh = __float2bfloat16(hn);
        g_hbf_hi[p ^ 1][L][b][j] = hh;
        g_hbf_lo[p ^ 1][L][b][j] = __float2bfloat16(hn - __bfloat162float(hh));
        if (L) out[((size_t)b * TT + t) * HH + j] = hn;
    }
}

// ---------------------------------------------------------------------------
extern "C" void kernel_launch(void* const* d_in, const int* in_sizes, int n_in,
                              void* d_out, int out_size)
{
    const float* x     = (const float*)d_in[0];
    const float* mask  = (const float*)d_in[1];
    const float* W_ih0 = (const float*)d_in[2];
    const float* W_hh0 = (const float*)d_in[3];
    const float* bs0   = (const float*)d_in[4];
    const float* W_ih1 = (const float*)d_in[5];
    const float* W_hh1 = (const float*)d_in[6];
    const float* bs1   = (const float*)d_in[7];
    float* out = (float*)d_out;

    prep_weights<<<dim3(KK / 32, C4 / 32, 2), dim3(32, 8)>>>(W_ih0, W_hh0, W_ih1, W_hh1);
    swizzle_weights<<<(2 * NGRP * 4 * NCHUNK * 32) / 256, 256>>>();
    prep_x<<<1024, 256>>>(x);
    zero_states<<<512, 256>>>();

    for (int t = 0; t < TT; t++) {
        lstm_step<<<128, 128>>>(t, mask, bs0, bs1, out);
    }

    if (out_size >= BZ * TT * HH + BZ * TT) {
        copy_mask<<<(BZ * TT + 255) / 256, 256>>>(mask, out + (size_t)BZ * TT * HH);
    }
}

// round 3
// speedup vs baseline: 3.6375x; 3.2510x over previous
#include <cuda_runtime.h>
#include <cuda_bf16.h>
#include <math.h>

// Problem constants
#define BZ 32
#define TT 256
#define EE 1024
#define HH 1024
#define KK 2048   // per-layer K: [h_prev ; other] (other = x_t for L0, h1_prev for L1)
#define C4 4096   // 4*H gate columns per layer
#define NGRP 64           // m-groups per layer (4096 / 64)
#define NCHUNK (KK / 16)  // 128 k-chunks of 16

// ---------------------------------------------------------------------------
// Scratch (device globals; no allocations allowed)
// ---------------------------------------------------------------------------
__device__ __nv_bfloat16 g_Wt_hi[2][C4][KK];
__device__ __nv_bfloat16 g_Wt_lo[2][C4][KK];
// Fragment-swizzled weights: index ((((L*64+g)*4+w)*128+c)*32+lane),
// each uint4 = the 4 .b32 words of one lane's m16n8k16 A fragment.
__device__ uint4 g_Wsw_hi[2 * NGRP * 4 * NCHUNK * 32];
__device__ uint4 g_Wsw_lo[2 * NGRP * 4 * NCHUNK * 32];
// x re-laid-out as [t*32 + b][e], split hi/lo
__device__ __nv_bfloat16 g_x_hi[TT * BZ][EE];
__device__ __nv_bfloat16 g_x_lo[TT * BZ][EE];
// hidden states as bf16 hi/lo, ping-pong on parity
__device__ __nv_bfloat16 g_hbf_hi[2][2][BZ][HH];   // [parity][layer][b][j]
__device__ __nv_bfloat16 g_hbf_lo[2][2][BZ][HH];
// fp32 master states
__device__ float g_h[2][BZ][HH];
__device__ float g_c[2][BZ][HH];

// ---------------------------------------------------------------------------
// Helpers
// ---------------------------------------------------------------------------
__device__ __forceinline__ unsigned ldu(const __nv_bfloat16* p) {
    return *reinterpret_cast<const unsigned*>(p);
}

__device__ __forceinline__ void mma16816(float d[4], const unsigned* a,
                                         unsigned b0, unsigned b1) {
    asm volatile(
        "mma.sync.aligned.m16n8k16.row.col.f32.bf16.bf16.f32 "
        "{%0,%1,%2,%3}, {%4,%5,%6,%7}, {%8,%9}, {%0,%1,%2,%3};\n"
        : "+f"(d[0]), "+f"(d[1]), "+f"(d[2]), "+f"(d[3])
        : "r"(a[0]), "r"(a[1]), "r"(a[2]), "r"(a[3]), "r"(b0), "r"(b1));
}

__device__ __forceinline__ void ldm4(unsigned r[4], unsigned addr) {
    asm volatile("ldmatrix.sync.aligned.m8n8.x4.shared.b16 {%0,%1,%2,%3}, [%4];"
                 : "=r"(r[0]), "=r"(r[1]), "=r"(r[2]), "=r"(r[3]) : "r"(addr));
}

__device__ __forceinline__ float sigf(float x) {
    return 1.f / (1.f + __expf(-x));
}
__device__ __forceinline__ float tanhfast(float x) {
    float e2 = __expf(-2.f * fabsf(x));
    float t = (1.f - e2) / (1.f + e2);
    return copysignf(t, x);
}

// ---------------------------------------------------------------------------
// Prep kernels
// ---------------------------------------------------------------------------
__global__ void prep_weights(const float* __restrict__ W_ih0,
                             const float* __restrict__ W_hh0,
                             const float* __restrict__ W_ih1,
                             const float* __restrict__ W_hh1)
{
    __shared__ float tile[32][33];
    int k0 = blockIdx.x * 32;
    int c0 = blockIdx.y * 32;
    int L  = blockIdx.z;
    int tx = threadIdx.x, ty = threadIdx.y;
#pragma unroll
    for (int i = 0; i < 4; i++) {
        int k = k0 + ty + i * 8;
        const float* S; int kr;
        if (L == 0) { if (k < HH) { S = W_hh0; kr = k; } else { S = W_ih0; kr = k - HH; } }
        else        { if (k < HH) { S = W_ih1; kr = k; } else { S = W_hh1; kr = k - HH; } }
        tile[ty + i * 8][tx] = S[(size_t)kr * C4 + c0 + tx];
    }
    __syncthreads();
#pragma unroll
    for (int i = 0; i < 4; i++) {
        int c = c0 + ty + i * 8;
        float v = tile[tx][ty + i * 8];
        __nv_bfloat16 hi = __float2bfloat16(v);
        g_Wt_hi[L][c][k0 + tx] = hi;
        g_Wt_lo[L][c][k0 + tx] = __float2bfloat16(v - __bfloat162float(hi));
    }
}

__global__ void swizzle_weights()
{
    const int idx = blockIdx.x * blockDim.x + threadIdx.x;
    const int lane = idx & 31;
    const int c    = (idx >> 5)  & (NCHUNK - 1);
    const int w    = (idx >> 12) & 3;
    const int g    = (idx >> 14) & (NGRP - 1);
    const int L    = (idx >> 20) & 1;

    const int r  = lane >> 2;
    const int ka = (lane & 3) * 2;
    const int col0 = w * HH + g * 16 + r;
    const int col1 = col0 + 8;
    const int k0 = c * 16 + ka;

    uint4 hi, lo;
    hi.x = ldu(&g_Wt_hi[L][col0][k0]);
    hi.y = ldu(&g_Wt_hi[L][col1][k0]);
    hi.z = ldu(&g_Wt_hi[L][col0][k0 + 8]);
    hi.w = ldu(&g_Wt_hi[L][col1][k0 + 8]);
    lo.x = ldu(&g_Wt_lo[L][col0][k0]);
    lo.y = ldu(&g_Wt_lo[L][col1][k0]);
    lo.z = ldu(&g_Wt_lo[L][col0][k0 + 8]);
    lo.w = ldu(&g_Wt_lo[L][col1][k0 + 8]);
    g_Wsw_hi[idx] = hi;
    g_Wsw_lo[idx] = lo;
}

__global__ void prep_x(const float* __restrict__ x)
{
    const int N = BZ * TT * EE;
    for (int idx = blockIdx.x * blockDim.x + threadIdx.x; idx < N;
         idx += gridDim.x * blockDim.x) {
        int e  = idx & (EE - 1);
        int bt = idx >> 10;
        int t  = bt & (TT - 1);
        int b  = bt >> 8;
        float v = x[idx];
        __nv_bfloat16 hi = __float2bfloat16(v);
        size_t d = ((size_t)t * BZ + b) * EE + e;
        (&g_x_hi[0][0])[d] = hi;
        (&g_x_lo[0][0])[d] = __float2bfloat16(v - __bfloat162float(hi));
    }
}

__global__ void zero_states()
{
    int idx = blockIdx.x * blockDim.x + threadIdx.x;
    const int nbf = 2 * 2 * BZ * HH;
    if (idx < nbf) {
        (&g_hbf_hi[0][0][0][0])[idx] = __float2bfloat16(0.f);
        (&g_hbf_lo[0][0][0][0])[idx] = __float2bfloat16(0.f);
    }
    const int nf = 2 * BZ * HH;
    if (idx < nf) {
        (&g_h[0][0][0])[idx] = 0.f;
        (&g_c[0][0][0])[idx] = 0.f;
    }
}

__global__ void copy_mask(const float* __restrict__ m, float* __restrict__ dst)
{
    int i = blockIdx.x * blockDim.x + threadIdx.x;
    if (i < BZ * TT) dst[i] = m[i];
}

// ---------------------------------------------------------------------------
// One timestep. 128 blocks x 256 threads (8 warps), one wave.
// Block bx: L = bx>>6, unit group g = bx&63 (units [g*16, g*16+16)).
// Warp (w = gate, hf = k-half). B tiles staged in SMEM (cp.async, double
// buffered), read via ldmatrix. Partial preactivations reduced via SMEM
// (aliased over the B buffers), then fused pointwise LSTM update.
// ---------------------------------------------------------------------------
#define SM_BYTES 36864            // 2 buf * 2 half * 2 hilo * 32 n * 72 k * 2B
#define BUF_STRIDE (4 * 32 * 72 * 2)

__global__ void __launch_bounds__(256) lstm_step(
    int t,
    const float* __restrict__ mask,
    const float* __restrict__ bias0,
    const float* __restrict__ bias1,
    float* __restrict__ out)
{
    __shared__ __align__(16) unsigned char smraw[SM_BYTES];
    float* preS = reinterpret_cast<float*>(smraw);   // aliased after B use: [2][64][33]

    const int bx   = blockIdx.x;
    const int L    = bx >> 6;
    const int g    = bx & (NGRP - 1);
    const int tid  = threadIdx.x;
    const int lane = tid & 31;
    const int warp = tid >> 5;
    const int w    = warp & 3;     // gate
    const int hf   = warp >> 2;    // k-half
    const int p    = t & 1;

    // Staging sources: half0 = h0(prev); half1 = x_t (L0) or h1(prev) (L1)
    const __nv_bfloat16* __restrict__ s00 = &g_hbf_hi[p][0][0][0];
    const __nv_bfloat16* __restrict__ s01 = &g_hbf_lo[p][0][0][0];
    const __nv_bfloat16* __restrict__ s10 = L ? &g_hbf_hi[p][1][0][0]
                                              : &g_x_hi[(size_t)t * BZ][0];
    const __nv_bfloat16* __restrict__ s11 = L ? &g_hbf_lo[p][1][0][0]
                                              : &g_x_lo[(size_t)t * BZ][0];

    const unsigned smbase = (unsigned)__cvta_generic_to_shared(smraw);

    // --- B tile staging: 1024 cp.async of 16B per tile (64k x 32n, hi+lo, 2 halves)
    auto stage = [&](int nt, int buf) {
#pragma unroll
        for (int q = 0; q < 4; q++) {
            int idx  = tid + q * 256;
            int half = idx >> 9;
            int hilo = (idx >> 8) & 1;
            int row  = (idx >> 3) & 31;
            int colc = idx & 7;
            const __nv_bfloat16* sb = half ? (hilo ? s11 : s10) : (hilo ? s01 : s00);
            const __nv_bfloat16* src = sb + (size_t)row * HH + nt * 64 + colc * 8;
            unsigned dst = smbase +
                ((((buf * 4 + half * 2 + hilo) * 32 + row) * 72 + colc * 8) << 1);
            asm volatile("cp.async.ca.shared.global [%0], [%1], 16;\n"
                         :: "r"(dst), "l"(src));
        }
        asm volatile("cp.async.commit_group;\n");
    };

    // A fragment pointers (swizzled; one LDG.128 per chunk per lane)
    const uint4* __restrict__ Ahi =
        g_Wsw_hi + ((size_t)((L * NGRP + g) * 4 + w) * NCHUNK) * 32 + lane;
    const uint4* __restrict__ Alo =
        g_Wsw_lo + ((size_t)((L * NGRP + g) * 4 + w) * NCHUNK) * 32 + lane;
    const int cbase = hf * 64;   // this warp's chunk base

    // ldmatrix per-lane addresses: tile = lane>>3 -> (n-subtile, k-subtile)
    const int ltile = lane >> 3;
    const int lrow  = lane & 7;
    const int nbb   = (ltile >> 1) * 8 + lrow;
    const int kb    = (ltile & 1) * 8;
    unsigned ldm_off[2][2];   // [hilo][ngrp]
#pragma unroll
    for (int hilo = 0; hilo < 2; hilo++)
#pragma unroll
        for (int ng = 0; ng < 2; ng++)
            ldm_off[hilo][ng] = smbase +
                ((((hf * 2 + hilo) * 32 + ng * 16 + nbb) * 72 + kb) << 1);

    float acc[4][4];
#pragma unroll
    for (int j = 0; j < 4; j++)
#pragma unroll
        for (int q = 0; q < 4; q++) acc[j][q] = 0.f;

    // A register double buffer
    uint4 AH[4], AL[4], AHn[4], ALn[4];
#pragma unroll
    for (int cc = 0; cc < 4; cc++) {
        AH[cc] = Ahi[(cbase + cc) * 32];
        AL[cc] = Alo[(cbase + cc) * 32];
    }

    stage(0, 0);

    for (int nt = 0; nt < 16; nt++) {
        const int buf = nt & 1;
        if (nt < 15) {
#pragma unroll
            for (int cc = 0; cc < 4; cc++) {
                AHn[cc] = Ahi[(cbase + (nt + 1) * 4 + cc) * 32];
                ALn[cc] = Alo[(cbase + (nt + 1) * 4 + cc) * 32];
            }
            stage(nt + 1, buf ^ 1);
            asm volatile("cp.async.wait_group 1;\n");
        } else {
            asm volatile("cp.async.wait_group 0;\n");
        }
        __syncthreads();

        const unsigned bufoff = buf * BUF_STRIDE;
#pragma unroll
        for (int cc = 0; cc < 4; cc++) {
            const unsigned kco = cc * 32;   // 16 k elems * 2B
            unsigned bh[4], bh2[4], bl[4], bl2[4];
            ldm4(bh,  ldm_off[0][0] + bufoff + kco);
            ldm4(bh2, ldm_off[0][1] + bufoff + kco);
            ldm4(bl,  ldm_off[1][0] + bufoff + kco);
            ldm4(bl2, ldm_off[1][1] + bufoff + kco);
            const unsigned* ap = reinterpret_cast<const unsigned*>(&AH[cc]);
            const unsigned* lp = reinterpret_cast<const unsigned*>(&AL[cc]);
            mma16816(acc[0], ap, bh[0], bh[1]);
            mma16816(acc[0], ap, bl[0], bl[1]);
            mma16816(acc[0], lp, bh[0], bh[1]);
            mma16816(acc[1], ap, bh[2], bh[3]);
            mma16816(acc[1], ap, bl[2], bl[3]);
            mma16816(acc[1], lp, bh[2], bh[3]);
            mma16816(acc[2], ap, bh2[0], bh2[1]);
            mma16816(acc[2], ap, bl2[0], bl2[1]);
            mma16816(acc[2], lp, bh2[0], bh2[1]);
            mma16816(acc[3], ap, bh2[2], bh2[3]);
            mma16816(acc[3], ap, bl2[2], bl2[3]);
            mma16816(acc[3], lp, bh2[2], bh2[3]);
        }
#pragma unroll
        for (int cc = 0; cc < 4; cc++) { AH[cc] = AHn[cc]; AL[cc] = ALn[cc]; }
        __syncthreads();
    }

    // Scatter partial preactivations (preS aliases the B buffers; all B reads done)
    {
        const int r = lane >> 2;
        const int q = (lane & 3) * 2;
        float* pS = preS + hf * (64 * 33);
#pragma unroll
        for (int j = 0; j < 4; j++) {
            const int n = j * 8 + q;
            pS[(w * 16 + r) * 33 + n]           = acc[j][0];
            pS[(w * 16 + r) * 33 + n + 1]       = acc[j][1];
            pS[(w * 16 + r + 8) * 33 + n]       = acc[j][2];
            pS[(w * 16 + r + 8) * 33 + n + 1]   = acc[j][3];
        }
    }
    __syncthreads();

    // Fused pointwise LSTM cell update: 16 units x 32 batch
    const float* __restrict__ bias = L ? bias1 : bias0;
#pragma unroll
    for (int e = tid; e < 512; e += 256) {
        const int b  = e >> 4;
        const int ul = e & 15;
        const int j  = g * 16 + ul;
        float f  = preS[ul * 33 + b]        + preS[64 * 33 + ul * 33 + b]        + bias[j];
        float i  = preS[(16 + ul) * 33 + b] + preS[64 * 33 + (16 + ul) * 33 + b] + bias[HH + j];
        float o  = preS[(32 + ul) * 33 + b] + preS[64 * 33 + (32 + ul) * 33 + b] + bias[2 * HH + j];
        float gg = preS[(48 + ul) * 33 + b] + preS[64 * 33 + (48 + ul) * 33 + b] + bias[3 * HH + j];
        const float m  = mask[b * TT + t];
        const float cp = g_c[L][b][j];
        const float hp = g_h[L][b][j];

        float cn = sigf(f) * cp + sigf(i) * tanhfast(gg);
        cn = cn * m + cp * (1.f - m);
        float hn = sigf(o) * tanhfast(cn);
        hn = hn * m + hp * (1.f - m);

        g_c[L][b][j] = cn;
        g_h[L][b][j] = hn;
        const __nv_bfloat16 hh = __float2bfloat16(hn);
        g_hbf_hi[p ^ 1][L][b][j] = hh;
        g_hbf_lo[p ^ 1][L][b][j] = __float2bfloat16(hn - __bfloat162float(hh));
        if (L) out[((size_t)b * TT + t) * HH + j] = hn;
    }
}

// ---------------------------------------------------------------------------
extern "C" void kernel_launch(void* const* d_in, const int* in_sizes, int n_in,
                              void* d_out, int out_size)
{
    const float* x     = (const float*)d_in[0];
    const float* mask  = (const float*)d_in[1];
    const float* W_ih0 = (const float*)d_in[2];
    const float* W_hh0 = (const float*)d_in[3];
    const float* bs0   = (const float*)d_in[4];
    const float* W_ih1 = (const float*)d_in[5];
    const float* W_hh1 = (const float*)d_in[6];
    const float* bs1   = (const float*)d_in[7];
    float* out = (float*)d_out;

    prep_weights<<<dim3(KK / 32, C4 / 32, 2), dim3(32, 8)>>>(W_ih0, W_hh0, W_ih1, W_hh1);
    swizzle_weights<<<(2 * NGRP * 4 * NCHUNK * 32) / 256, 256>>>();
    prep_x<<<1024, 256>>>(x);
    zero_states<<<512, 256>>>();

    for (int t = 0; t < TT; t++) {
        lstm_step<<<128, 256>>>(t, mask, bs0, bs1, out);
    }

    if (out_size >= BZ * TT * HH + BZ * TT) {
        copy_mask<<<(BZ * TT + 255) / 256, 256>>>(mask, out + (size_t)BZ * TT * HH);
    }
}

// round 4
// speedup vs baseline: 7.8925x; 2.1698x over previous
#include <cuda_runtime.h>
#include <cuda_fp16.h>
#include <math.h>

// Problem constants
#define BZ 32
#define TT 256
#define EE 1024
#define HH 1024
#define KK 2048
#define C4 4096
#define NMT 256           // m-tiles (16 cols) per layer
#define NCHUNK 128        // k-chunks of 16
#define BROW 1032         // staged B row stride in halves (2064 B, conflict-free)
#define BMATB 66048       // bytes per staged 32x1024 fp16 matrix (32*1032*2)

// ---------------------------------------------------------------------------
// Device scratch (static; no allocations)
// ---------------------------------------------------------------------------
__device__ __half g_Wt[2][C4][KK];            // transposed weights, fp16
__device__ uint4  g_Wsw[2 * NMT * NCHUNK * 32]; // mma A fragments
__device__ __half g_x[TT * BZ][EE];           // x re-laid [t*32+b][e]
__device__ __half g_hf[2][2][BZ][HH];         // [parity][layer][b][j]
__device__ float  g_h[2][BZ][HH];
__device__ float  g_c[2][BZ][HH];
__device__ float  g_X0[(size_t)TT * C4 * BZ]; // x@W_ih0 + b0, [t][col][b]

// ---------------------------------------------------------------------------
// Helpers
// ---------------------------------------------------------------------------
__device__ __forceinline__ unsigned ldu(const __half* p) {
    return *reinterpret_cast<const unsigned*>(p);
}
__device__ __forceinline__ void mma16816(float d[4], const unsigned* a,
                                         unsigned b0, unsigned b1) {
    asm volatile(
        "mma.sync.aligned.m16n8k16.row.col.f32.f16.f16.f32 "
        "{%0,%1,%2,%3}, {%4,%5,%6,%7}, {%8,%9}, {%0,%1,%2,%3};\n"
        : "+f"(d[0]), "+f"(d[1]), "+f"(d[2]), "+f"(d[3])
        : "r"(a[0]), "r"(a[1]), "r"(a[2]), "r"(a[3]), "r"(b0), "r"(b1));
}
__device__ __forceinline__ void ldm4(unsigned r[4], unsigned addr) {
    asm volatile("ldmatrix.sync.aligned.m8n8.x4.shared.b16 {%0,%1,%2,%3}, [%4];"
                 : "=r"(r[0]), "=r"(r[1]), "=r"(r[2]), "=r"(r[3]) : "r"(addr));
}
__device__ __forceinline__ float sigf(float x) { return 1.f / (1.f + __expf(-x)); }
__device__ __forceinline__ float tanhfast(float x) {
    float e2 = __expf(-2.f * fabsf(x));
    return copysignf((1.f - e2) / (1.f + e2), x);
}

// ---------------------------------------------------------------------------
// Prep kernels
// ---------------------------------------------------------------------------
__global__ void prep_weights(const float* __restrict__ W_ih0,
                             const float* __restrict__ W_hh0,
                             const float* __restrict__ W_ih1,
                             const float* __restrict__ W_hh1)
{
    __shared__ float tile[32][33];
    int k0 = blockIdx.x * 32;
    int c0 = blockIdx.y * 32;
    int L  = blockIdx.z;
    int tx = threadIdx.x, ty = threadIdx.y;
#pragma unroll
    for (int i = 0; i < 4; i++) {
        int k = k0 + ty + i * 8;
        const float* S; int kr;
        if (L == 0) { if (k < HH) { S = W_hh0; kr = k; } else { S = W_ih0; kr = k - HH; } }
        else        { if (k < HH) { S = W_ih1; kr = k; } else { S = W_hh1; kr = k - HH; } }
        tile[ty + i * 8][tx] = S[(size_t)kr * C4 + c0 + tx];
    }
    __syncthreads();
#pragma unroll
    for (int i = 0; i < 4; i++) {
        int c = c0 + ty + i * 8;
        g_Wt[L][c][k0 + tx] = __float2half(tile[tx][ty + i * 8]);
    }
}

__global__ void swizzle_weights()
{
    const int idx  = blockIdx.x * blockDim.x + threadIdx.x;
    const int lane = idx & 31;
    const int c    = (idx >> 5)  & (NCHUNK - 1);
    const int mt   = (idx >> 12) & (NMT - 1);
    const int L    = (idx >> 20) & 1;
    const int r  = lane >> 2;
    const int ka = (lane & 3) * 2;
    const int col0 = mt * 16 + r;
    const int col1 = col0 + 8;
    const int k0 = c * 16 + ka;
    uint4 f;
    f.x = ldu(&g_Wt[L][col0][k0]);
    f.y = ldu(&g_Wt[L][col1][k0]);
    f.z = ldu(&g_Wt[L][col0][k0 + 8]);
    f.w = ldu(&g_Wt[L][col1][k0 + 8]);
    g_Wsw[idx] = f;
}

__global__ void prep_x(const float* __restrict__ x)
{
    const int N = BZ * TT * EE;
    for (int idx = blockIdx.x * blockDim.x + threadIdx.x; idx < N;
         idx += gridDim.x * blockDim.x) {
        int e  = idx & (EE - 1);
        int bt = idx >> 10;
        int t  = bt & (TT - 1);
        int b  = bt >> 8;
        g_x[t * BZ + b][e] = __float2half(x[idx]);
    }
}

__global__ void zero_states()
{
    int idx = blockIdx.x * blockDim.x + threadIdx.x;
    const int nhf = 2 * 2 * BZ * HH;
    if (idx < nhf) (&g_hf[0][0][0][0])[idx] = __float2half(0.f);
    const int nf = 2 * BZ * HH;
    if (idx < nf) {
        (&g_h[0][0][0])[idx] = 0.f;
        (&g_c[0][0][0])[idx] = 0.f;
    }
}

__global__ void copy_mask(const float* __restrict__ m, float* __restrict__ dst)
{
    int i = blockIdx.x * blockDim.x + threadIdx.x;
    if (i < BZ * TT) dst[i] = m[i];
}

// ---------------------------------------------------------------------------
// X0 precompute: X0[t][col][b] = sum_e x[t,b,e]*W_ih0[e,col] + b0[col]
// Grid (64 col-groups, 32 t-groups), 256 threads: warp = (gate w, n-half nh).
// Uses L0's swizzled chunks 64..127 (the W_ih0 half).
// ---------------------------------------------------------------------------
__global__ void __launch_bounds__(256) x0_gemm(const float* __restrict__ b0)
{
    extern __shared__ __align__(16) unsigned char sm[];
    const unsigned smbase = (unsigned)__cvta_generic_to_shared(sm);
    const int gX  = blockIdx.x;
    const int ty  = blockIdx.y;
    const int tid = threadIdx.x, lane = tid & 31, warp = tid >> 5;
    const int w = warp & 3, nh = warp >> 2;
    const int mt = w * 64 + gX;

    const uint4* __restrict__ A = g_Wsw + ((size_t)mt * NCHUNK + 64) * 32 + lane;

    const int ltile = lane >> 3, lrow = lane & 7;
    const int nbb = (ltile >> 1) * 8 + lrow;
    const int kb  = (ltile & 1) * 8;
    const unsigned ldmb = smbase + (((nh * 16 + nbb) * BROW + kb) << 1);

    const int colr = mt * 16 + (lane >> 2);
    const float bia0 = b0[colr];
    const float bia8 = b0[colr + 8];

    for (int tt = 0; tt < 8; tt++) {
        const int t = ty * 8 + tt;
        // stage x_t rows (32 x 1024 fp16) into padded SMEM
#pragma unroll
        for (int q = 0; q < 16; q++) {
            int idx = tid + q * 256;
            int row = idx >> 7, kc = idx & 127;
            const __half* src = &g_x[t * BZ + row][kc * 8];
            unsigned dst = smbase + row * 2064 + kc * 16;
            asm volatile("cp.async.ca.shared.global [%0], [%1], 16;\n"
                         :: "r"(dst), "l"(src));
        }
        asm volatile("cp.async.commit_group;\ncp.async.wait_group 0;\n");
        __syncthreads();

        float acc0[4] = {0, 0, 0, 0}, acc1[4] = {0, 0, 0, 0};
        uint4 Ac[4], An[4];
#pragma unroll
        for (int cc = 0; cc < 4; cc++) Ac[cc] = A[cc * 32];
        for (int ct = 0; ct < 16; ct++) {
            if (ct < 15) {
#pragma unroll
                for (int cc = 0; cc < 4; cc++) An[cc] = A[((ct + 1) * 4 + cc) * 32];
            }
#pragma unroll
            for (int cc = 0; cc < 4; cc++) {
                const int c = ct * 4 + cc;
                unsigned bb[4];
                ldm4(bb, ldmb + c * 32);
                const unsigned* ap = reinterpret_cast<const unsigned*>(&Ac[cc]);
                mma16816(acc0, ap, bb[0], bb[1]);
                mma16816(acc1, ap, bb[2], bb[3]);
            }
#pragma unroll
            for (int cc = 0; cc < 4; cc++) Ac[cc] = An[cc];
        }
        __syncthreads();   // before next t's staging overwrites B

        const size_t base = (size_t)t * C4 * BZ;
        const int bc0 = nh * 16 + (lane & 3) * 2;
        g_X0[base + (size_t)colr * 32 + bc0]           = acc0[0] + bia0;
        g_X0[base + (size_t)colr * 32 + bc0 + 1]       = acc0[1] + bia0;
        g_X0[base + (size_t)(colr + 8) * 32 + bc0]     = acc0[2] + bia8;
        g_X0[base + (size_t)(colr + 8) * 32 + bc0 + 1] = acc0[3] + bia8;
        const int bc1 = bc0 + 8;
        g_X0[base + (size_t)colr * 32 + bc1]           = acc1[0] + bia0;
        g_X0[base + (size_t)colr * 32 + bc1 + 1]       = acc1[1] + bia0;
        g_X0[base + (size_t)(colr + 8) * 32 + bc1]     = acc1[2] + bia8;
        g_X0[base + (size_t)(colr + 8) * 32 + bc1 + 1] = acc1[3] + bia8;
    }
}

// ---------------------------------------------------------------------------
// One timestep. 128 blocks x 256 threads.
//   bx <  64: layer0, g=bx,   64 cols, K=1024 (W_hh0 · h0; x-part precomputed)
//   bx >= 64: layer1, g=bx-64, 64 cols, K=2048 (W_ih1 · h0 ; W_hh1 · h1)
// Warp (w = gate, hf = k-half). B staged ONCE per step in SMEM; single-pass
// mma with register A prefetch; fused pointwise update.
// ---------------------------------------------------------------------------
__global__ void __launch_bounds__(256) lstm_step(
    int t,
    const float* __restrict__ mask,
    const float* __restrict__ bias1,
    float* __restrict__ out)
{
    extern __shared__ __align__(16) unsigned char sm[];
    const unsigned smbase = (unsigned)__cvta_generic_to_shared(sm);
    float* preS = reinterpret_cast<float*>(sm);    // aliased after mma: [2][64][33]

    const int bx   = blockIdx.x;
    const int L    = bx >> 6;
    const int g    = bx & 63;
    const int tid  = threadIdx.x;
    const int lane = tid & 31;
    const int warp = tid >> 5;
    const int w    = warp & 3;
    const int hf   = warp >> 2;
    const int p    = t & 1;

    // ---- stage B (h matrices) once ----
    const __half* __restrict__ h0 = &g_hf[p][0][0][0];
    const __half* __restrict__ h1 = &g_hf[p][1][0][0];
    if (L == 0) {
#pragma unroll
        for (int q = 0; q < 16; q++) {
            int idx = tid + q * 256;
            int row = idx >> 7, kc = idx & 127;
            const __half* src = h0 + row * HH + kc * 8;
            unsigned dst = smbase + row * 2064 + kc * 16;
            asm volatile("cp.async.ca.shared.global [%0], [%1], 16;\n"
                         :: "r"(dst), "l"(src));
        }
    } else {
#pragma unroll
        for (int q = 0; q < 32; q++) {
            int idx = tid + q * 256;
            int mat = idx >> 12;
            int row = (idx >> 7) & 31, kc = idx & 127;
            const __half* src = (mat ? h1 : h0) + row * HH + kc * 8;
            unsigned dst = smbase + mat * BMATB + row * 2064 + kc * 16;
            asm volatile("cp.async.ca.shared.global [%0], [%1], 16;\n"
                         :: "r"(dst), "l"(src));
        }
    }
    asm volatile("cp.async.commit_group;\ncp.async.wait_group 0;\n");
    __syncthreads();

    // ---- mma ----
    const int mt      = w * 64 + g;
    const int nchunks = L ? 64 : 32;
    const int cbase   = L ? hf * 64 : hf * 32;
    const uint4* __restrict__ A =
        g_Wsw + (((size_t)L * NMT + mt) * NCHUNK + cbase) * 32 + lane;

    const int ltile = lane >> 3, lrow = lane & 7;
    const int nbb = (ltile >> 1) * 8 + lrow;
    const int kb  = (ltile & 1) * 8;
    const unsigned matoff = L ? hf * BMATB : hf * 1024;   // L0: k-half offset in bytes
    unsigned ldmb[2];
#pragma unroll
    for (int ng = 0; ng < 2; ng++)
        ldmb[ng] = smbase + matoff + (((ng * 16 + nbb) * BROW + kb) << 1);

    float acc[4][4];
#pragma unroll
    for (int j = 0; j < 4; j++)
#pragma unroll
        for (int q = 0; q < 4; q++) acc[j][q] = 0.f;

    uint4 Ac[4], An[4];
#pragma unroll
    for (int cc = 0; cc < 4; cc++) Ac[cc] = A[cc * 32];
    const int niter = nchunks >> 2;
    for (int ct = 0; ct < niter; ct++) {
        if (ct + 1 < niter) {
#pragma unroll
            for (int cc = 0; cc < 4; cc++) An[cc] = A[((ct + 1) * 4 + cc) * 32];
        }
#pragma unroll
        for (int cc = 0; cc < 4; cc++) {
            const int c = ct * 4 + cc;
            unsigned b01[4], b23[4];
            ldm4(b01, ldmb[0] + c * 32);
            ldm4(b23, ldmb[1] + c * 32);
            const unsigned* ap = reinterpret_cast<const unsigned*>(&Ac[cc]);
            mma16816(acc[0], ap, b01[0], b01[1]);
            mma16816(acc[1], ap, b01[2], b01[3]);
            mma16816(acc[2], ap, b23[0], b23[1]);
            mma16816(acc[3], ap, b23[2], b23[3]);
        }
#pragma unroll
        for (int cc = 0; cc < 4; cc++) Ac[cc] = An[cc];
    }
    __syncthreads();   // all B reads done before aliasing preS over it

    // ---- reduce partials via SMEM ----
    {
        const int r = lane >> 2;
        const int q = (lane & 3) * 2;
        float* pS = preS + hf * (64 * 33);
#pragma unroll
        for (int j = 0; j < 4; j++) {
            const int n = j * 8 + q;
            pS[(w * 16 + r) * 33 + n]         = acc[j][0];
            pS[(w * 16 + r) * 33 + n + 1]     = acc[j][1];
            pS[(w * 16 + r + 8) * 33 + n]     = acc[j][2];
            pS[(w * 16 + r + 8) * 33 + n + 1] = acc[j][3];
        }
    }
    __syncthreads();

    // ---- fused pointwise LSTM update: 16 units x 32 batch ----
#pragma unroll
    for (int e = tid; e < 512; e += 256) {
        const int b  = e >> 4;
        const int ul = e & 15;
        const int j  = g * 16 + ul;
        float f  = preS[ul * 33 + b]        + preS[64 * 33 + ul * 33 + b];
        float i  = preS[(16 + ul) * 33 + b] + preS[64 * 33 + (16 + ul) * 33 + b];
        float o  = preS[(32 + ul) * 33 + b] + preS[64 * 33 + (32 + ul) * 33 + b];
        float gg = preS[(48 + ul) * 33 + b] + preS[64 * 33 + (48 + ul) * 33 + b];
        if (L == 0) {
            const size_t xb = (size_t)t * C4 * BZ + b;
            f  += g_X0[xb + (size_t)j * 32];
            i  += g_X0[xb + (size_t)(HH + j) * 32];
            o  += g_X0[xb + (size_t)(2 * HH + j) * 32];
            gg += g_X0[xb + (size_t)(3 * HH + j) * 32];
        } else {
            f  += bias1[j];
            i  += bias1[HH + j];
            o  += bias1[2 * HH + j];
            gg += bias1[3 * HH + j];
        }
        const float m  = mask[b * TT + t];
        const float cp = g_c[L][b][j];
        const float hp = g_h[L][b][j];

        float cn = sigf(f) * cp + sigf(i) * tanhfast(gg);
        cn = cn * m + cp * (1.f - m);
        float hn = sigf(o) * tanhfast(cn);
        hn = hn * m + hp * (1.f - m);

        g_c[L][b][j] = cn;
        g_h[L][b][j] = hn;
        g_hf[p ^ 1][L][b][j] = __float2half(hn);
        if (L) out[((size_t)b * TT + t) * HH + j] = hn;
    }
}

// ---------------------------------------------------------------------------
extern "C" void kernel_launch(void* const* d_in, const int* in_sizes, int n_in,
                              void* d_out, int out_size)
{
    const float* x     = (const float*)d_in[0];
    const float* mask  = (const float*)d_in[1];
    const float* W_ih0 = (const float*)d_in[2];
    const float* W_hh0 = (const float*)d_in[3];
    const float* bs0   = (const float*)d_in[4];
    const float* W_ih1 = (const float*)d_in[5];
    const float* W_hh1 = (const float*)d_in[6];
    const float* bs1   = (const float*)d_in[7];
    float* out = (float*)d_out;

    static bool attr_done = false;
    if (!attr_done) {
        cudaFuncSetAttribute(x0_gemm, cudaFuncAttributeMaxDynamicSharedMemorySize, BMATB);
        cudaFuncSetAttribute(lstm_step, cudaFuncAttributeMaxDynamicSharedMemorySize, 2 * BMATB);
        attr_done = true;
    }

    prep_weights<<<dim3(KK / 32, C4 / 32, 2), dim3(32, 8)>>>(W_ih0, W_hh0, W_ih1, W_hh1);
    swizzle_weights<<<(2 * NMT * NCHUNK * 32) / 256, 256>>>();
    prep_x<<<1024, 256>>>(x);
    zero_states<<<512, 256>>>();
    x0_gemm<<<dim3(64, 32), 256, BMATB>>>(bs0);

    for (int t = 0; t < TT; t++) {
        lstm_step<<<128, 256, 2 * BMATB>>>(t, mask, bs1, out);
    }

    if (out_size >= BZ * TT * HH + BZ * TT) {
        copy_mask<<<(BZ * TT + 255) / 256, 256>>>(mask, out + (size_t)BZ * TT * HH);
    }
}